// round 1
// baseline (speedup 1.0000x reference)
#include <cuda_runtime.h>
#include <math.h>

#define D_    768
#define P_    2048
#define B_    4
#define H_    12
#define DFF_  3072
#define NTOK  (B_ * P_)      /* 8192 */
#define D3_   (3 * D_)       /* 2304 */
#define EPS_  1e-3f
#define SURV_ 0.9f

// ---------------- scratch (static device globals; no runtime allocation) ----
__device__ float g_h  [NTOK * D_];    // LN output (reused for LN1 and LN2)
__device__ float g_qkv[NTOK * D3_];   // fused QKV projection
__device__ float g_x1 [NTOK * D_];    // attn residual output
__device__ float g_ffn[NTOK * DFF_];  // MLP hidden

// ---------------- LayerNorm: one block (256 threads) per row of 768 ---------
__global__ void __launch_bounds__(256) ln_kernel(
    const float* __restrict__ x, const float* __restrict__ g,
    const float* __restrict__ b, float* __restrict__ out)
{
    const int row = blockIdx.x;
    const int t   = threadIdx.x;
    const float* xr = x + (size_t)row * D_;

    float v0 = xr[t], v1 = xr[t + 256], v2 = xr[t + 512];
    float s = v0 + v1 + v2;

    __shared__ float red[8];
    __shared__ float mu_s, rs_s;

    #pragma unroll
    for (int o = 16; o; o >>= 1) s += __shfl_xor_sync(0xffffffffu, s, o);
    if ((t & 31) == 0) red[t >> 5] = s;
    __syncthreads();
    if (t < 32) {
        float tot = (t < 8) ? red[t] : 0.f;
        #pragma unroll
        for (int o = 4; o; o >>= 1) tot += __shfl_xor_sync(0xffffffffu, tot, o);
        if (t == 0) mu_s = tot * (1.0f / D_);
    }
    __syncthreads();
    const float mu = mu_s;

    float d0 = v0 - mu, d1 = v1 - mu, d2 = v2 - mu;
    float q = d0 * d0 + d1 * d1 + d2 * d2;
    #pragma unroll
    for (int o = 16; o; o >>= 1) q += __shfl_xor_sync(0xffffffffu, q, o);
    if ((t & 31) == 0) red[t >> 5] = q;
    __syncthreads();
    if (t < 32) {
        float tq = (t < 8) ? red[t] : 0.f;
        #pragma unroll
        for (int o = 4; o; o >>= 1) tq += __shfl_xor_sync(0xffffffffu, tq, o);
        if (t == 0) rs_s = rsqrtf(tq * (1.0f / D_) + EPS_);
    }
    __syncthreads();
    const float rs = rs_s;

    float* orow = out + (size_t)row * D_;
    orow[t]       = d0 * rs * g[t]       + b[t];
    orow[t + 256] = d1 * rs * g[t + 256] + b[t + 256];
    orow[t + 512] = d2 * rs * g[t + 512] + b[t + 512];
}

// ---------------- SGEMM: C = A[M,K] @ B[K,N] + bias, with epilogue ----------
// 128x128 block tile, BK=8, 256 threads, 8x8 microtile per thread.
// EPI: 0 = bias only; 1 = bias + exact GELU; 2 = bias, *0.9 + residual.
#define BM 128
#define BN 128
#define BK 8
#define TM 8
#define TN 8

template <int EPI>
__global__ void __launch_bounds__(256) sgemm_kernel(
    const float* __restrict__ A, const float* __restrict__ B,
    const float* __restrict__ bias, const float* __restrict__ res,
    float* __restrict__ C, int M, int N, int K)
{
    __shared__ float As[BK][BM];
    __shared__ float Bs[BK][BN];

    const int tid = threadIdx.x;
    const int bn  = blockIdx.x, bm = blockIdx.y;
    const int tx  = tid & 15, ty = tid >> 4;

    const float* Ab = A + (size_t)bm * BM * K;
    const float* Bb = B + (size_t)bn * BN;

    const int arow = tid >> 1, acol = (tid & 1) * 4;   // A: 128x8 via 256 float4
    const int brow = tid >> 5, bcol = (tid & 31) * 4;  // B: 8x128 via 256 float4

    float acc[TM][TN];
    #pragma unroll
    for (int i = 0; i < TM; i++)
        #pragma unroll
        for (int j = 0; j < TN; j++) acc[i][j] = 0.f;

    for (int k0 = 0; k0 < K; k0 += BK) {
        float4 av = *(const float4*)(Ab + (size_t)arow * K + k0 + acol);
        As[acol + 0][arow] = av.x;
        As[acol + 1][arow] = av.y;
        As[acol + 2][arow] = av.z;
        As[acol + 3][arow] = av.w;
        float4 bv = *(const float4*)(Bb + (size_t)(k0 + brow) * N + bcol);
        *(float4*)&Bs[brow][bcol] = bv;
        __syncthreads();

        #pragma unroll
        for (int k = 0; k < BK; k++) {
            float4 a0 = *(const float4*)&As[k][ty * TM];
            float4 a1 = *(const float4*)&As[k][ty * TM + 4];
            float4 b0 = *(const float4*)&Bs[k][tx * TN];
            float4 b1 = *(const float4*)&Bs[k][tx * TN + 4];
            float a[TM] = {a0.x, a0.y, a0.z, a0.w, a1.x, a1.y, a1.z, a1.w};
            float bb[TN] = {b0.x, b0.y, b0.z, b0.w, b1.x, b1.y, b1.z, b1.w};
            #pragma unroll
            for (int i = 0; i < TM; i++)
                #pragma unroll
                for (int j = 0; j < TN; j++)
                    acc[i][j] += a[i] * bb[j];
        }
        __syncthreads();
    }

    const int crow0 = bm * BM + ty * TM;
    const int ccol0 = bn * BN + tx * TN;
    #pragma unroll
    for (int i = 0; i < TM; i++) {
        const size_t roff = (size_t)(crow0 + i) * N;
        #pragma unroll
        for (int j = 0; j < TN; j++) {
            const int c = ccol0 + j;
            float v = acc[i][j] + bias[c];
            if (EPI == 1) {
                v = 0.5f * v * (1.0f + erff(v * 0.70710678118654752f));
            } else if (EPI == 2) {
                v = v * SURV_ + res[roff + c];
            }
            C[roff + c] = v;
        }
    }
}

// ---------------- Flash attention (fp32), fused residual -------------------
// One block per (q_tile of 64, head, batch). 256 threads.
// O = softmax(Q Kt / 8) V ; writes x1 = O*0.9 + x  (head h owns cols h*64..)
#define QT  64
#define HD  64
#define PAD 68
#define FLASH_SMEM ((4 * QT * PAD + 3 * QT) * (int)sizeof(float))

__global__ void __launch_bounds__(256) flash_kernel(
    const float* __restrict__ qkv, const float* __restrict__ x,
    float* __restrict__ x1)
{
    extern __shared__ float sm[];
    float* Qs  = sm;                 // [64][PAD]
    float* Ks  = Qs + QT * PAD;
    float* Vs  = Ks + QT * PAD;
    float* Ss  = Vs + QT * PAD;      // scores / probs [64][PAD]
    float* m_s = Ss + QT * PAD;      // [64]
    float* l_s = m_s + QT;
    float* f_s = l_s + QT;

    const int t  = threadIdx.x;
    const int qt = blockIdx.x, h = blockIdx.y, b = blockIdx.z;
    const size_t base = (size_t)b * P_ * D3_;
    const int q0 = qt * QT;
    const int hc = h * HD;

    // load Q tile, pre-scaled by 1/sqrt(hd)=1/8
    #pragma unroll
    for (int j = 0; j < 4; j++) {
        int idx = t + j * 256;
        int r = idx >> 4, c4 = (idx & 15) << 2;
        float4 v = *(const float4*)(qkv + base + (size_t)(q0 + r) * D3_ + hc + c4);
        float* dst = &Qs[r * PAD + c4];
        dst[0] = v.x * 0.125f; dst[1] = v.y * 0.125f;
        dst[2] = v.z * 0.125f; dst[3] = v.w * 0.125f;
    }
    if (t < QT) { m_s[t] = -1e30f; l_s[t] = 0.f; }

    const int tx = t & 15, ty = t >> 4;
    float o[4][4];
    #pragma unroll
    for (int i = 0; i < 4; i++)
        #pragma unroll
        for (int j = 0; j < 4; j++) o[i][j] = 0.f;

    for (int kt = 0; kt < P_ / QT; kt++) {
        __syncthreads();  // previous tile's consumers done; Q/m/l visible (iter 0)
        const int k0 = kt * QT;
        #pragma unroll
        for (int j = 0; j < 4; j++) {
            int idx = t + j * 256;
            int r = idx >> 4, c4 = (idx & 15) << 2;
            float4 kv = *(const float4*)(qkv + base + (size_t)(k0 + r) * D3_ + D_ + hc + c4);
            *(float4*)&Ks[r * PAD + c4] = kv;
            float4 vv = *(const float4*)(qkv + base + (size_t)(k0 + r) * D3_ + 2 * D_ + hc + c4);
            *(float4*)&Vs[r * PAD + c4] = vv;
        }
        __syncthreads();

        // S = Qs @ Ks^T : thread owns q rows {ty+16i}, k cols {tx+16j}
        float s[4][4];
        #pragma unroll
        for (int i = 0; i < 4; i++)
            #pragma unroll
            for (int j = 0; j < 4; j++) s[i][j] = 0.f;
        #pragma unroll
        for (int c = 0; c < HD; c++) {
            float a[4], bb[4];
            #pragma unroll
            for (int i = 0; i < 4; i++) a[i] = Qs[(ty + i * 16) * PAD + c];
            #pragma unroll
            for (int j = 0; j < 4; j++) bb[j] = Ks[(tx + j * 16) * PAD + c];
            #pragma unroll
            for (int i = 0; i < 4; i++)
                #pragma unroll
                for (int j = 0; j < 4; j++) s[i][j] += a[i] * bb[j];
        }
        #pragma unroll
        for (int i = 0; i < 4; i++)
            #pragma unroll
            for (int j = 0; j < 4; j++)
                Ss[(ty + i * 16) * PAD + tx + j * 16] = s[i][j];
        __syncthreads();

        // online softmax: 4 threads per row, 16 cols each
        {
            const int r = t >> 2, seg = t & 3;
            float* srow = &Ss[r * PAD + seg * 16];
            float pm = -1e30f;
            #pragma unroll
            for (int k = 0; k < 16; k++) pm = fmaxf(pm, srow[k]);
            pm = fmaxf(pm, __shfl_xor_sync(0xffffffffu, pm, 1));
            pm = fmaxf(pm, __shfl_xor_sync(0xffffffffu, pm, 2));
            const float mold = m_s[r];
            const float mnew = fmaxf(mold, pm);
            float ps = 0.f;
            #pragma unroll
            for (int k = 0; k < 16; k++) {
                float e = __expf(srow[k] - mnew);
                srow[k] = e;
                ps += e;
            }
            ps += __shfl_xor_sync(0xffffffffu, ps, 1);
            ps += __shfl_xor_sync(0xffffffffu, ps, 2);
            if (seg == 0) {
                float f = __expf(mold - mnew);
                m_s[r] = mnew;
                l_s[r] = l_s[r] * f + ps;
                f_s[r] = f;
            }
        }
        __syncthreads();

        // O = O*f + P @ V
        float fr[4];
        #pragma unroll
        for (int i = 0; i < 4; i++) fr[i] = f_s[ty + i * 16];
        #pragma unroll
        for (int i = 0; i < 4; i++)
            #pragma unroll
            for (int j = 0; j < 4; j++) o[i][j] *= fr[i];
        #pragma unroll
        for (int kk = 0; kk < QT; kk++) {
            float a[4], bb[4];
            #pragma unroll
            for (int i = 0; i < 4; i++) a[i] = Ss[(ty + i * 16) * PAD + kk];
            #pragma unroll
            for (int j = 0; j < 4; j++) bb[j] = Vs[kk * PAD + tx + j * 16];
            #pragma unroll
            for (int i = 0; i < 4; i++)
                #pragma unroll
                for (int j = 0; j < 4; j++) o[i][j] += a[i] * bb[j];
        }
    }

    // finalize: divide by l, apply droppath scale, add residual x
    float linv[4];
    #pragma unroll
    for (int i = 0; i < 4; i++) linv[i] = 1.0f / l_s[ty + i * 16];
    #pragma unroll
    for (int i = 0; i < 4; i++) {
        const int r = q0 + ty + i * 16;
        const size_t rowoff = ((size_t)b * P_ + r) * D_ + hc;
        #pragma unroll
        for (int j = 0; j < 4; j++) {
            const int c = tx + j * 16;
            x1[rowoff + c] = o[i][j] * linv[i] * SURV_ + x[rowoff + c];
        }
    }
}

// ---------------- launch ----------------------------------------------------
extern "C" void kernel_launch(void* const* d_in, const int* in_sizes, int n_in,
                              void* d_out, int out_size)
{
    const float* x     = (const float*)d_in[0];
    const float* ln1_g = (const float*)d_in[1];
    const float* ln1_b = (const float*)d_in[2];
    const float* w_qkv = (const float*)d_in[3];
    const float* b_qkv = (const float*)d_in[4];
    const float* ln2_g = (const float*)d_in[5];
    const float* ln2_b = (const float*)d_in[6];
    const float* w1    = (const float*)d_in[7];
    const float* b1    = (const float*)d_in[8];
    const float* w2    = (const float*)d_in[9];
    const float* b2    = (const float*)d_in[10];
    float* out = (float*)d_out;

    float *h, *qkv, *x1, *ffn;
    cudaGetSymbolAddress((void**)&h,   g_h);
    cudaGetSymbolAddress((void**)&qkv, g_qkv);
    cudaGetSymbolAddress((void**)&x1,  g_x1);
    cudaGetSymbolAddress((void**)&ffn, g_ffn);

    cudaFuncSetAttribute(flash_kernel,
                         cudaFuncAttributeMaxDynamicSharedMemorySize, FLASH_SMEM);

    // 1) LN1
    ln_kernel<<<NTOK, 256>>>(x, ln1_g, ln1_b, h);
    // 2) QKV projection: [8192,768] @ [768,2304]
    sgemm_kernel<0><<<dim3(D3_ / BN, NTOK / BM), 256>>>(h, w_qkv, b_qkv, nullptr,
                                                        qkv, NTOK, D3_, D_);
    // 3) attention + residual -> x1
    flash_kernel<<<dim3(P_ / QT, H_, B_), 256, FLASH_SMEM>>>(qkv, x, x1);
    // 4) LN2
    ln_kernel<<<NTOK, 256>>>(x1, ln2_g, ln2_b, h);
    // 5) MLP up + GELU: [8192,768] @ [768,3072]
    sgemm_kernel<1><<<dim3(DFF_ / BN, NTOK / BM), 256>>>(h, w1, b1, nullptr,
                                                         ffn, NTOK, DFF_, D_);
    // 6) MLP down + droppath + residual: [8192,3072] @ [3072,768]
    sgemm_kernel<2><<<dim3(D_ / BN, NTOK / BM), 256>>>(ffn, w2, b2, x1,
                                                       out, NTOK, D_, DFF_);
}

// round 3
// speedup vs baseline: 1.7009x; 1.7009x over previous
#include <cuda_runtime.h>
#include <cuda_bf16.h>
#include <math.h>
#include <stdint.h>

#define D_    768
#define P_    2048
#define B_    4
#define H_    12
#define DFF_  3072
#define NTOK  (B_ * P_)      /* 8192 */
#define D3_   (3 * D_)       /* 2304 */
#define EPS_  1e-3f
#define SURV_ 0.9f

// ---------------- scratch (static device globals) ---------------------------
__device__ __nv_bfloat16 g_h_hi [NTOK * D_];
__device__ __nv_bfloat16 g_h_lo [NTOK * D_];
__device__ float         g_qkv  [NTOK * D3_];
__device__ float         g_x1   [NTOK * D_];
__device__ __nv_bfloat16 g_ffn_hi[NTOK * DFF_];
__device__ __nv_bfloat16 g_ffn_lo[NTOK * DFF_];
// transposed+split weights: [N, K] layout
__device__ __nv_bfloat16 g_wq_hi[D3_ * D_],  g_wq_lo[D3_ * D_];
__device__ __nv_bfloat16 g_w1_hi[DFF_ * D_], g_w1_lo[DFF_ * D_];
__device__ __nv_bfloat16 g_w2_hi[D_ * DFF_], g_w2_lo[D_ * DFF_];

// ---------------- helpers ----------------------------------------------------
__device__ __forceinline__ uint32_t smem_u32(const void* p) {
    uint32_t a;
    asm("{ .reg .u64 t; cvta.to.shared.u64 t, %1; cvt.u32.u64 %0, t; }"
        : "=r"(a) : "l"(p));
    return a;
}
__device__ __forceinline__ void ldsm_x4(uint32_t* r, uint32_t addr) {
    asm volatile("ldmatrix.sync.aligned.m8n8.x4.shared.b16 {%0,%1,%2,%3}, [%4];"
                 : "=r"(r[0]), "=r"(r[1]), "=r"(r[2]), "=r"(r[3]) : "r"(addr));
}
__device__ __forceinline__ void mma16816(float* c, const uint32_t* a,
                                         uint32_t b0, uint32_t b1) {
    asm volatile(
        "mma.sync.aligned.m16n8k16.row.col.f32.bf16.bf16.f32 "
        "{%0,%1,%2,%3}, {%4,%5,%6,%7}, {%8,%9}, {%0,%1,%2,%3};"
        : "+f"(c[0]), "+f"(c[1]), "+f"(c[2]), "+f"(c[3])
        : "r"(a[0]), "r"(a[1]), "r"(a[2]), "r"(a[3]), "r"(b0), "r"(b1));
}

// ---------------- LayerNorm + bf16 hi/lo split -------------------------------
__global__ void __launch_bounds__(256) ln_split_kernel(
    const float* __restrict__ x, const float* __restrict__ g,
    const float* __restrict__ b,
    __nv_bfloat16* __restrict__ hi, __nv_bfloat16* __restrict__ lo)
{
    const int row = blockIdx.x;
    const int t   = threadIdx.x;
    const float* xr = x + (size_t)row * D_;

    float v0 = xr[t], v1 = xr[t + 256], v2 = xr[t + 512];
    float s = v0 + v1 + v2;

    __shared__ float red[8];
    __shared__ float mu_s, rs_s;

    #pragma unroll
    for (int o = 16; o; o >>= 1) s += __shfl_xor_sync(0xffffffffu, s, o);
    if ((t & 31) == 0) red[t >> 5] = s;
    __syncthreads();
    if (t < 32) {
        float tot = (t < 8) ? red[t] : 0.f;
        #pragma unroll
        for (int o = 4; o; o >>= 1) tot += __shfl_xor_sync(0xffffffffu, tot, o);
        if (t == 0) mu_s = tot * (1.0f / D_);
    }
    __syncthreads();
    const float mu = mu_s;

    float d0 = v0 - mu, d1 = v1 - mu, d2 = v2 - mu;
    float q = d0 * d0 + d1 * d1 + d2 * d2;
    #pragma unroll
    for (int o = 16; o; o >>= 1) q += __shfl_xor_sync(0xffffffffu, q, o);
    if ((t & 31) == 0) red[t >> 5] = q;
    __syncthreads();
    if (t < 32) {
        float tq = (t < 8) ? red[t] : 0.f;
        #pragma unroll
        for (int o = 4; o; o >>= 1) tq += __shfl_xor_sync(0xffffffffu, tq, o);
        if (t == 0) rs_s = rsqrtf(tq * (1.0f / D_) + EPS_);
    }
    __syncthreads();
    const float rs = rs_s;

    const size_t ro = (size_t)row * D_;
    #pragma unroll
    for (int j = 0; j < 3; j++) {
        const int c = t + j * 256;
        const float dj = (j == 0 ? d0 : (j == 1 ? d1 : d2));
        float v = dj * rs * g[c] + b[c];
        __nv_bfloat16 h = __float2bfloat16(v);
        hi[ro + c] = h;
        lo[ro + c] = __float2bfloat16(v - __bfloat162float(h));
    }
}

// ---------------- weight transpose + split: w[K,N] -> wt_{hi,lo}[N,K] -------
__global__ void __launch_bounds__(256) wsplit_kernel(
    const float* __restrict__ w, __nv_bfloat16* __restrict__ hi,
    __nv_bfloat16* __restrict__ lo, int K, int N)
{
    __shared__ float t[32][33];
    const int n0 = blockIdx.x * 32, k0 = blockIdx.y * 32;
    const int tx = threadIdx.x & 31, ty = threadIdx.x >> 5;
    #pragma unroll
    for (int j = 0; j < 4; j++) {
        int k = ty + j * 8;
        t[k][tx] = w[(size_t)(k0 + k) * N + n0 + tx];
    }
    __syncthreads();
    #pragma unroll
    for (int j = 0; j < 4; j++) {
        int n = ty + j * 8;
        float v = t[tx][n];
        __nv_bfloat16 h = __float2bfloat16(v);
        size_t o = (size_t)(n0 + n) * K + k0 + tx;
        hi[o] = h;
        lo[o] = __float2bfloat16(v - __bfloat162float(h));
    }
}

// ---------------- MMA GEMM: C[M,N] = (Ahi+Alo)[M,K] @ (Bhi+Blo)[N,K]^T ------
// 128x128 block tile, K chunk 32 (bf16), 8 warps (4m x 2n), warp = 32x64.
// hi/lo split: acc += Ahi*Bhi + Ahi*Blo + Alo*Bhi (fp32 accumulate).
// EPI: 0 bias->fp32 ; 1 bias+GELU->bf16 hi/lo ; 2 bias,*0.9+res->fp32
#define BM   128
#define BN   128
#define BKC  32
#define LDT  40           /* halves per smem row: 32 + 8 pad */
#define ROWB (LDT * 2)    /* 80 bytes */

template <int EPI>
__global__ void __launch_bounds__(256, 2) gemm_mma(
    const __nv_bfloat16* __restrict__ Ahi_g, const __nv_bfloat16* __restrict__ Alo_g,
    const __nv_bfloat16* __restrict__ Bhi_g, const __nv_bfloat16* __restrict__ Blo_g,
    const float* __restrict__ bias, const float* __restrict__ res,
    float* __restrict__ Cf,
    __nv_bfloat16* __restrict__ Chi, __nv_bfloat16* __restrict__ Clo,
    int M, int N, int K)
{
    __shared__ __align__(16) __nv_bfloat16 sA[2][BM][LDT];
    __shared__ __align__(16) __nv_bfloat16 sB[2][BN][LDT];

    const int tid  = threadIdx.x;
    const int lane = tid & 31;
    const int wid  = tid >> 5;
    const int wm   = wid & 3;       // warp row  (32 rows each)
    const int wn   = wid >> 2;      // warp col  (64 cols each)
    const int m0   = blockIdx.y * BM;
    const int n0   = blockIdx.x * BN;

    // ldmatrix lane addressing
    const int a_row = lane & 15;
    const int a_col = (lane >> 4) << 3;
    const uint32_t aHi = smem_u32(&sA[0][wm * 32 + a_row][a_col]);
    const uint32_t aLo = smem_u32(&sA[1][wm * 32 + a_row][a_col]);
    const int b_row = (lane & 7) | ((lane >> 4) << 3);
    const int b_col = ((lane >> 3) & 1) << 3;
    const uint32_t bHi = smem_u32(&sB[0][wn * 64 + b_row][b_col]);
    const uint32_t bLo = smem_u32(&sB[1][wn * 64 + b_row][b_col]);

    float acc[2][8][4];
    #pragma unroll
    for (int i = 0; i < 2; i++)
        #pragma unroll
        for (int j = 0; j < 8; j++)
            #pragma unroll
            for (int k = 0; k < 4; k++) acc[i][j][k] = 0.f;

    const int ldu = K >> 3;  // row stride in uint4
    const uint4* gah = (const uint4*)Ahi_g;
    const uint4* gal = (const uint4*)Alo_g;
    const uint4* gbh = (const uint4*)Bhi_g;
    const uint4* gbl = (const uint4*)Blo_g;

    const int nchunks = K / BKC;
    for (int ch = 0; ch < nchunks; ch++) {
        const int k0u = ch * (BKC / 8);
        // load 4 tiles: 512 uint4 each, 2 per thread per tile
        #pragma unroll
        for (int i = 0; i < 2; i++) {
            const int idx = tid + i * 256;
            const int r = idx >> 2, q = idx & 3;
            ((uint4*)&sA[0][r][0])[q] = gah[(size_t)(m0 + r) * ldu + k0u + q];
            ((uint4*)&sA[1][r][0])[q] = gal[(size_t)(m0 + r) * ldu + k0u + q];
            ((uint4*)&sB[0][r][0])[q] = gbh[(size_t)(n0 + r) * ldu + k0u + q];
            ((uint4*)&sB[1][r][0])[q] = gbl[(size_t)(n0 + r) * ldu + k0u + q];
        }
        __syncthreads();

        #pragma unroll
        for (int ks = 0; ks < BKC; ks += 16) {
            uint32_t ah[2][4], al[2][4];
            #pragma unroll
            for (int mt = 0; mt < 2; mt++) {
                ldsm_x4(ah[mt], aHi + mt * (16 * ROWB) + ks * 2);
                ldsm_x4(al[mt], aLo + mt * (16 * ROWB) + ks * 2);
            }
            #pragma unroll
            for (int np = 0; np < 4; np++) {
                uint32_t bh[4], bl[4];
                ldsm_x4(bh, bHi + np * (16 * ROWB) + ks * 2);
                ldsm_x4(bl, bLo + np * (16 * ROWB) + ks * 2);
                #pragma unroll
                for (int mt = 0; mt < 2; mt++) {
                    mma16816(acc[mt][2 * np],     ah[mt], bh[0], bh[1]);
                    mma16816(acc[mt][2 * np + 1], ah[mt], bh[2], bh[3]);
                    mma16816(acc[mt][2 * np],     al[mt], bh[0], bh[1]);
                    mma16816(acc[mt][2 * np + 1], al[mt], bh[2], bh[3]);
                    mma16816(acc[mt][2 * np],     ah[mt], bl[0], bl[1]);
                    mma16816(acc[mt][2 * np + 1], ah[mt], bl[2], bl[3]);
                }
            }
        }
        __syncthreads();
    }

    // epilogue: c0,c1 -> row lr, cols lc,lc+1 ; c2,c3 -> row lr+8
    const int lr = lane >> 2;
    const int lc = (lane & 3) * 2;
    #pragma unroll
    for (int mt = 0; mt < 2; mt++) {
        #pragma unroll
        for (int nt = 0; nt < 8; nt++) {
            #pragma unroll
            for (int hh = 0; hh < 2; hh++) {
                const int gr = m0 + wm * 32 + mt * 16 + lr + hh * 8;
                const int gc = n0 + wn * 64 + nt * 8 + lc;
                float v0 = acc[mt][nt][hh * 2 + 0] + bias[gc];
                float v1 = acc[mt][nt][hh * 2 + 1] + bias[gc + 1];
                const size_t go = (size_t)gr * N + gc;
                if (EPI == 1) {
                    v0 = 0.5f * v0 * (1.0f + erff(v0 * 0.70710678118654752f));
                    v1 = 0.5f * v1 * (1.0f + erff(v1 * 0.70710678118654752f));
                    __nv_bfloat16 h0 = __float2bfloat16(v0);
                    __nv_bfloat16 h1 = __float2bfloat16(v1);
                    __nv_bfloat16 l0 = __float2bfloat16(v0 - __bfloat162float(h0));
                    __nv_bfloat16 l1 = __float2bfloat16(v1 - __bfloat162float(h1));
                    uint32_t ph = (uint32_t)__bfloat16_as_ushort(h0) |
                                  ((uint32_t)__bfloat16_as_ushort(h1) << 16);
                    uint32_t pl = (uint32_t)__bfloat16_as_ushort(l0) |
                                  ((uint32_t)__bfloat16_as_ushort(l1) << 16);
                    ((uint32_t*)Chi)[go >> 1] = ph;
                    ((uint32_t*)Clo)[go >> 1] = pl;
                } else if (EPI == 2) {
                    float2 rr = *(const float2*)&res[go];
                    float2 o2 = make_float2(v0 * SURV_ + rr.x, v1 * SURV_ + rr.y);
                    *(float2*)&Cf[go] = o2;
                } else {
                    *(float2*)&Cf[go] = make_float2(v0, v1);
                }
            }
        }
    }
}

// ---------------- Flash attention (fp32), fused residual -------------------
#define QT  64
#define HD  64
#define PAD 68
#define FLASH_SMEM ((4 * QT * PAD + 3 * QT) * (int)sizeof(float))

__global__ void __launch_bounds__(256) flash_kernel(
    const float* __restrict__ qkv, const float* __restrict__ x,
    float* __restrict__ x1)
{
    extern __shared__ float sm[];
    float* Qs  = sm;
    float* Ks  = Qs + QT * PAD;
    float* Vs  = Ks + QT * PAD;
    float* Ss  = Vs + QT * PAD;
    float* m_s = Ss + QT * PAD;
    float* l_s = m_s + QT;
    float* f_s = l_s + QT;

    const int t  = threadIdx.x;
    const int qt = blockIdx.x, h = blockIdx.y, b = blockIdx.z;
    const size_t base = (size_t)b * P_ * D3_;
    const int q0 = qt * QT;
    const int hc = h * HD;

    #pragma unroll
    for (int j = 0; j < 4; j++) {
        int idx = t + j * 256;
        int r = idx >> 4, c4 = (idx & 15) << 2;
        float4 v = *(const float4*)(qkv + base + (size_t)(q0 + r) * D3_ + hc + c4);
        float* dst = &Qs[r * PAD + c4];
        dst[0] = v.x * 0.125f; dst[1] = v.y * 0.125f;
        dst[2] = v.z * 0.125f; dst[3] = v.w * 0.125f;
    }
    if (t < QT) { m_s[t] = -1e30f; l_s[t] = 0.f; }

    const int tx = t & 15, ty = t >> 4;
    float o[4][4];
    #pragma unroll
    for (int i = 0; i < 4; i++)
        #pragma unroll
        for (int j = 0; j < 4; j++) o[i][j] = 0.f;

    for (int kt = 0; kt < P_ / QT; kt++) {
        __syncthreads();
        const int k0 = kt * QT;
        #pragma unroll
        for (int j = 0; j < 4; j++) {
            int idx = t + j * 256;
            int r = idx >> 4, c4 = (idx & 15) << 2;
            float4 kv = *(const float4*)(qkv + base + (size_t)(k0 + r) * D3_ + D_ + hc + c4);
            *(float4*)&Ks[r * PAD + c4] = kv;
            float4 vv = *(const float4*)(qkv + base + (size_t)(k0 + r) * D3_ + 2 * D_ + hc + c4);
            *(float4*)&Vs[r * PAD + c4] = vv;
        }
        __syncthreads();

        float s[4][4];
        #pragma unroll
        for (int i = 0; i < 4; i++)
            #pragma unroll
            for (int j = 0; j < 4; j++) s[i][j] = 0.f;
        #pragma unroll
        for (int c = 0; c < HD; c++) {
            float a[4], bb[4];
            #pragma unroll
            for (int i = 0; i < 4; i++) a[i] = Qs[(ty + i * 16) * PAD + c];
            #pragma unroll
            for (int j = 0; j < 4; j++) bb[j] = Ks[(tx + j * 16) * PAD + c];
            #pragma unroll
            for (int i = 0; i < 4; i++)
                #pragma unroll
                for (int j = 0; j < 4; j++) s[i][j] += a[i] * bb[j];
        }
        #pragma unroll
        for (int i = 0; i < 4; i++)
            #pragma unroll
            for (int j = 0; j < 4; j++)
                Ss[(ty + i * 16) * PAD + tx + j * 16] = s[i][j];
        __syncthreads();

        {
            const int r = t >> 2, seg = t & 3;
            float* srow = &Ss[r * PAD + seg * 16];
            float pm = -1e30f;
            #pragma unroll
            for (int k = 0; k < 16; k++) pm = fmaxf(pm, srow[k]);
            pm = fmaxf(pm, __shfl_xor_sync(0xffffffffu, pm, 1));
            pm = fmaxf(pm, __shfl_xor_sync(0xffffffffu, pm, 2));
            const float mold = m_s[r];
            const float mnew = fmaxf(mold, pm);
            float ps = 0.f;
            #pragma unroll
            for (int k = 0; k < 16; k++) {
                float e = __expf(srow[k] - mnew);
                srow[k] = e;
                ps += e;
            }
            ps += __shfl_xor_sync(0xffffffffu, ps, 1);
            ps += __shfl_xor_sync(0xffffffffu, ps, 2);
            if (seg == 0) {
                float f = __expf(mold - mnew);
                m_s[r] = mnew;
                l_s[r] = l_s[r] * f + ps;
                f_s[r] = f;
            }
        }
        __syncthreads();

        float fr[4];
        #pragma unroll
        for (int i = 0; i < 4; i++) fr[i] = f_s[ty + i * 16];
        #pragma unroll
        for (int i = 0; i < 4; i++)
            #pragma unroll
            for (int j = 0; j < 4; j++) o[i][j] *= fr[i];
        #pragma unroll
        for (int kk = 0; kk < QT; kk++) {
            float a[4], bb[4];
            #pragma unroll
            for (int i = 0; i < 4; i++) a[i] = Ss[(ty + i * 16) * PAD + kk];
            #pragma unroll
            for (int j = 0; j < 4; j++) bb[j] = Vs[kk * PAD + tx + j * 16];
            #pragma unroll
            for (int i = 0; i < 4; i++)
                #pragma unroll
                for (int j = 0; j < 4; j++) o[i][j] += a[i] * bb[j];
        }
    }

    float linv[4];
    #pragma unroll
    for (int i = 0; i < 4; i++) linv[i] = 1.0f / l_s[ty + i * 16];
    #pragma unroll
    for (int i = 0; i < 4; i++) {
        const int r = q0 + ty + i * 16;
        const size_t rowoff = ((size_t)b * P_ + r) * D_ + hc;
        #pragma unroll
        for (int j = 0; j < 4; j++) {
            const int c = tx + j * 16;
            x1[rowoff + c] = o[i][j] * linv[i] * SURV_ + x[rowoff + c];
        }
    }
}

// ---------------- launch ----------------------------------------------------
extern "C" void kernel_launch(void* const* d_in, const int* in_sizes, int n_in,
                              void* d_out, int out_size)
{
    const float* x     = (const float*)d_in[0];
    const float* ln1_g = (const float*)d_in[1];
    const float* ln1_b = (const float*)d_in[2];
    const float* w_qkv = (const float*)d_in[3];
    const float* b_qkv = (const float*)d_in[4];
    const float* ln2_g = (const float*)d_in[5];
    const float* ln2_b = (const float*)d_in[6];
    const float* w1    = (const float*)d_in[7];
    const float* b1    = (const float*)d_in[8];
    const float* w2    = (const float*)d_in[9];
    const float* b2    = (const float*)d_in[10];
    float* out = (float*)d_out;

    __nv_bfloat16 *h_hi, *h_lo, *ffn_hi, *ffn_lo;
    __nv_bfloat16 *wq_hi, *wq_lo, *w1_hi, *w1_lo, *w2_hi, *w2_lo;
    float *qkv, *x1;
    cudaGetSymbolAddress((void**)&h_hi,   g_h_hi);
    cudaGetSymbolAddress((void**)&h_lo,   g_h_lo);
    cudaGetSymbolAddress((void**)&qkv,    g_qkv);
    cudaGetSymbolAddress((void**)&x1,     g_x1);
    cudaGetSymbolAddress((void**)&ffn_hi, g_ffn_hi);
    cudaGetSymbolAddress((void**)&ffn_lo, g_ffn_lo);
    cudaGetSymbolAddress((void**)&wq_hi,  g_wq_hi);
    cudaGetSymbolAddress((void**)&wq_lo,  g_wq_lo);
    cudaGetSymbolAddress((void**)&w1_hi,  g_w1_hi);
    cudaGetSymbolAddress((void**)&w1_lo,  g_w1_lo);
    cudaGetSymbolAddress((void**)&w2_hi,  g_w2_hi);
    cudaGetSymbolAddress((void**)&w2_lo,  g_w2_lo);

    cudaFuncSetAttribute(flash_kernel,
                         cudaFuncAttributeMaxDynamicSharedMemorySize, FLASH_SMEM);

    // weight transpose + split (independent of activations)
    wsplit_kernel<<<dim3(D3_ / 32, D_ / 32), 256>>>(w_qkv, wq_hi, wq_lo, D_, D3_);
    wsplit_kernel<<<dim3(DFF_ / 32, D_ / 32), 256>>>(w1, w1_hi, w1_lo, D_, DFF_);
    wsplit_kernel<<<dim3(D_ / 32, DFF_ / 32), 256>>>(w2, w2_hi, w2_lo, DFF_, D_);

    // 1) LN1 -> split bf16
    ln_split_kernel<<<NTOK, 256>>>(x, ln1_g, ln1_b, h_hi, h_lo);
    // 2) QKV projection: [8192,768] x [2304,768]^T -> fp32
    gemm_mma<0><<<dim3(D3_ / BN, NTOK / BM), 256>>>(
        h_hi, h_lo, wq_hi, wq_lo, b_qkv, nullptr,
        qkv, nullptr, nullptr, NTOK, D3_, D_);
    // 3) attention + residual -> x1
    flash_kernel<<<dim3(P_ / QT, H_, B_), 256, FLASH_SMEM>>>(qkv, x, x1);
    // 4) LN2 -> split bf16
    ln_split_kernel<<<NTOK, 256>>>(x1, ln2_g, ln2_b, h_hi, h_lo);
    // 5) MLP up + GELU -> split bf16
    gemm_mma<1><<<dim3(DFF_ / BN, NTOK / BM), 256>>>(
        h_hi, h_lo, w1_hi, w1_lo, b1, nullptr,
        nullptr, ffn_hi, ffn_lo, NTOK, DFF_, D_);
    // 6) MLP down + droppath + residual -> out
    gemm_mma<2><<<dim3(D_ / BN, NTOK / BM), 256>>>(
        ffn_hi, ffn_lo, w2_hi, w2_lo, b2, x1,
        out, nullptr, nullptr, NTOK, D_, DFF_);
}

// round 4
// speedup vs baseline: 3.3729x; 1.9829x over previous
#include <cuda_runtime.h>
#include <cuda_bf16.h>
#include <math.h>
#include <stdint.h>

#define D_    768
#define P_    2048
#define B_    4
#define H_    12
#define DFF_  3072
#define NTOK  (B_ * P_)      /* 8192 */
#define D3_   (3 * D_)       /* 2304 */
#define EPS_  1e-3f
#define SURV_ 0.9f

// ---------------- scratch (static device globals) ---------------------------
__device__ __nv_bfloat16 g_h_hi [NTOK * D_];
__device__ __nv_bfloat16 g_h_lo [NTOK * D_];
__device__ __nv_bfloat16 g_qkvb [NTOK * D3_];   // bf16 QKV
__device__ float         g_x1   [NTOK * D_];
__device__ __nv_bfloat16 g_ffn_hi[NTOK * DFF_];
__device__ __nv_bfloat16 g_ffn_lo[NTOK * DFF_];
// transposed+split weights: [N, K] layout
__device__ __nv_bfloat16 g_wq_hi[D3_ * D_],  g_wq_lo[D3_ * D_];
__device__ __nv_bfloat16 g_w1_hi[DFF_ * D_], g_w1_lo[DFF_ * D_];
__device__ __nv_bfloat16 g_w2_hi[D_ * DFF_], g_w2_lo[D_ * DFF_];

// ---------------- helpers ----------------------------------------------------
__device__ __forceinline__ uint32_t smem_u32(const void* p) {
    uint32_t a;
    asm("{ .reg .u64 t; cvta.to.shared.u64 t, %1; cvt.u32.u64 %0, t; }"
        : "=r"(a) : "l"(p));
    return a;
}
__device__ __forceinline__ void ldsm_x4(uint32_t* r, uint32_t addr) {
    asm volatile("ldmatrix.sync.aligned.m8n8.x4.shared.b16 {%0,%1,%2,%3}, [%4];"
                 : "=r"(r[0]), "=r"(r[1]), "=r"(r[2]), "=r"(r[3]) : "r"(addr));
}
__device__ __forceinline__ void ldsm_x4_t(uint32_t* r, uint32_t addr) {
    asm volatile("ldmatrix.sync.aligned.m8n8.x4.trans.shared.b16 {%0,%1,%2,%3}, [%4];"
                 : "=r"(r[0]), "=r"(r[1]), "=r"(r[2]), "=r"(r[3]) : "r"(addr));
}
__device__ __forceinline__ void mma16816(float* c, const uint32_t* a,
                                         uint32_t b0, uint32_t b1) {
    asm volatile(
        "mma.sync.aligned.m16n8k16.row.col.f32.bf16.bf16.f32 "
        "{%0,%1,%2,%3}, {%4,%5,%6,%7}, {%8,%9}, {%0,%1,%2,%3};"
        : "+f"(c[0]), "+f"(c[1]), "+f"(c[2]), "+f"(c[3])
        : "r"(a[0]), "r"(a[1]), "r"(a[2]), "r"(a[3]), "r"(b0), "r"(b1));
}
__device__ __forceinline__ float ex2f(float x) {
    float y; asm("ex2.approx.f32 %0, %1;" : "=f"(y) : "f"(x)); return y;
}
// packed = {hi:hi_f, lo:lo_f}
__device__ __forceinline__ uint32_t pack_bf16x2(float lo, float hi) {
    uint32_t d;
    asm("cvt.rn.bf16x2.f32 %0, %1, %2;" : "=r"(d) : "f"(hi), "f"(lo));
    return d;
}
__device__ __forceinline__ void cp_async16(uint32_t dst, const void* src) {
    asm volatile("cp.async.cg.shared.global [%0], [%1], 16;"
                 :: "r"(dst), "l"(src));
}
#define CP_COMMIT() asm volatile("cp.async.commit_group;" ::: "memory")
#define CP_WAIT(n)  asm volatile("cp.async.wait_group %0;" :: "n"(n) : "memory")

// ---------------- LayerNorm + bf16 hi/lo split -------------------------------
__global__ void __launch_bounds__(256) ln_split_kernel(
    const float* __restrict__ x, const float* __restrict__ g,
    const float* __restrict__ b,
    __nv_bfloat16* __restrict__ hi, __nv_bfloat16* __restrict__ lo)
{
    const int row = blockIdx.x;
    const int t   = threadIdx.x;
    const float* xr = x + (size_t)row * D_;

    float v0 = xr[t], v1 = xr[t + 256], v2 = xr[t + 512];
    float s = v0 + v1 + v2;

    __shared__ float red[8];
    __shared__ float mu_s, rs_s;

    #pragma unroll
    for (int o = 16; o; o >>= 1) s += __shfl_xor_sync(0xffffffffu, s, o);
    if ((t & 31) == 0) red[t >> 5] = s;
    __syncthreads();
    if (t < 32) {
        float tot = (t < 8) ? red[t] : 0.f;
        #pragma unroll
        for (int o = 4; o; o >>= 1) tot += __shfl_xor_sync(0xffffffffu, tot, o);
        if (t == 0) mu_s = tot * (1.0f / D_);
    }
    __syncthreads();
    const float mu = mu_s;

    float d0 = v0 - mu, d1 = v1 - mu, d2 = v2 - mu;
    float q = d0 * d0 + d1 * d1 + d2 * d2;
    #pragma unroll
    for (int o = 16; o; o >>= 1) q += __shfl_xor_sync(0xffffffffu, q, o);
    if ((t & 31) == 0) red[t >> 5] = q;
    __syncthreads();
    if (t < 32) {
        float tq = (t < 8) ? red[t] : 0.f;
        #pragma unroll
        for (int o = 4; o; o >>= 1) tq += __shfl_xor_sync(0xffffffffu, tq, o);
        if (t == 0) rs_s = rsqrtf(tq * (1.0f / D_) + EPS_);
    }
    __syncthreads();
    const float rs = rs_s;

    const size_t ro = (size_t)row * D_;
    #pragma unroll
    for (int j = 0; j < 3; j++) {
        const int c = t + j * 256;
        const float dj = (j == 0 ? d0 : (j == 1 ? d1 : d2));
        float v = dj * rs * g[c] + b[c];
        __nv_bfloat16 h = __float2bfloat16(v);
        hi[ro + c] = h;
        lo[ro + c] = __float2bfloat16(v - __bfloat162float(h));
    }
}

// ---------------- weight transpose + split: w[K,N] -> wt_{hi,lo}[N,K] -------
__global__ void __launch_bounds__(256) wsplit_kernel(
    const float* __restrict__ w, __nv_bfloat16* __restrict__ hi,
    __nv_bfloat16* __restrict__ lo, int K, int N)
{
    __shared__ float t[32][33];
    const int n0 = blockIdx.x * 32, k0 = blockIdx.y * 32;
    const int tx = threadIdx.x & 31, ty = threadIdx.x >> 5;
    #pragma unroll
    for (int j = 0; j < 4; j++) {
        int k = ty + j * 8;
        t[k][tx] = w[(size_t)(k0 + k) * N + n0 + tx];
    }
    __syncthreads();
    #pragma unroll
    for (int j = 0; j < 4; j++) {
        int n = ty + j * 8;
        float v = t[tx][n];
        __nv_bfloat16 h = __float2bfloat16(v);
        size_t o = (size_t)(n0 + n) * K + k0 + tx;
        hi[o] = h;
        lo[o] = __float2bfloat16(v - __bfloat162float(h));
    }
}

// ---------------- MMA GEMM with cp.async 2-stage pipeline -------------------
// C[M,N] = (Ahi+Alo)[M,K] @ (Bhi+Blo)[N,K]^T ; 128x128 tile, K chunk 32.
// 8 warps (4m x 2n), warp = 32x64. acc += Ahi*Bhi + Ahi*Blo + Alo*Bhi.
// EPI: 1 bias+GELU->bf16 hi/lo ; 2 bias,*0.9+res->fp32 ; 3 bias->bf16
#define BM   128
#define BN   128
#define BKC  32
#define LDT  40           /* halves per smem row: 32 + 8 pad */
#define TILEB 10240       /* 128 * 80 bytes */
#define STAGEB 40960      /* 4 tiles */
#define GEMM_SMEM (2 * STAGEB)

template <int EPI>
__global__ void __launch_bounds__(256, 2) gemm_mma(
    const __nv_bfloat16* __restrict__ Ahi_g, const __nv_bfloat16* __restrict__ Alo_g,
    const __nv_bfloat16* __restrict__ Bhi_g, const __nv_bfloat16* __restrict__ Blo_g,
    const float* __restrict__ bias, const float* __restrict__ res,
    float* __restrict__ Cf,
    __nv_bfloat16* __restrict__ Chi, __nv_bfloat16* __restrict__ Clo,
    int M, int N, int K)
{
    extern __shared__ char dsm[];
    const uint32_t sbase = smem_u32(dsm);

    const int tid  = threadIdx.x;
    const int lane = tid & 31;
    const int wid  = tid >> 5;
    const int wm   = wid & 3;
    const int wn   = wid >> 2;
    const int m0   = blockIdx.y * BM;
    const int n0   = blockIdx.x * BN;

    // ldmatrix lane offsets (bytes within a stage)
    const int a_row = lane & 15;
    const int a_col = (lane >> 4) << 3;
    const uint32_t offA = (uint32_t)((wm * 32 + a_row) * 80 + a_col * 2);
    const int b_row = (lane & 7) | ((lane >> 4) << 3);
    const int b_col = ((lane >> 3) & 1) << 3;
    const uint32_t offB = (uint32_t)(20480 + (wn * 64 + b_row) * 80 + b_col * 2);

    float acc[2][8][4];
    #pragma unroll
    for (int i = 0; i < 2; i++)
        #pragma unroll
        for (int j = 0; j < 8; j++)
            #pragma unroll
            for (int k = 0; k < 4; k++) acc[i][j][k] = 0.f;

    const int ldu = K >> 3;  // row stride in uint4
    const uint4* gah = (const uint4*)Ahi_g;
    const uint4* gal = (const uint4*)Alo_g;
    const uint4* gbh = (const uint4*)Bhi_g;
    const uint4* gbl = (const uint4*)Blo_g;

    // per-thread load slots: 2 per tile
    const int r_0 = tid >> 2,        q_0 = tid & 3;
    const int r_1 = (tid + 256) >> 2, q_1 = (tid + 256) & 3;

    const int nchunks = K / BKC;

    // ---- issue stage (cp.async) ----
    auto issue = [&](int stage, int ch) {
        const int k0u = ch * (BKC / 8);
        const uint32_t so = sbase + (uint32_t)stage * STAGEB;
        {
            uint32_t d = so + (uint32_t)(r_0 * 80 + q_0 * 16);
            cp_async16(d,             gah + (size_t)(m0 + r_0) * ldu + k0u + q_0);
            cp_async16(d + TILEB,     gal + (size_t)(m0 + r_0) * ldu + k0u + q_0);
            cp_async16(d + 2 * TILEB, gbh + (size_t)(n0 + r_0) * ldu + k0u + q_0);
            cp_async16(d + 3 * TILEB, gbl + (size_t)(n0 + r_0) * ldu + k0u + q_0);
        }
        {
            uint32_t d = so + (uint32_t)(r_1 * 80 + q_1 * 16);
            cp_async16(d,             gah + (size_t)(m0 + r_1) * ldu + k0u + q_1);
            cp_async16(d + TILEB,     gal + (size_t)(m0 + r_1) * ldu + k0u + q_1);
            cp_async16(d + 2 * TILEB, gbh + (size_t)(n0 + r_1) * ldu + k0u + q_1);
            cp_async16(d + 3 * TILEB, gbl + (size_t)(n0 + r_1) * ldu + k0u + q_1);
        }
    };

    issue(0, 0);
    CP_COMMIT();

    for (int ch = 0; ch < nchunks; ch++) {
        if (ch + 1 < nchunks) {
            issue((ch + 1) & 1, ch + 1);
            CP_COMMIT();
            CP_WAIT(1);
        } else {
            CP_WAIT(0);
        }
        __syncthreads();

        const uint32_t st = sbase + (uint32_t)(ch & 1) * STAGEB;
        const uint32_t aHi = st + offA;
        const uint32_t aLo = aHi + TILEB;
        const uint32_t bHi = st + offB;
        const uint32_t bLo = bHi + TILEB;

        #pragma unroll
        for (int ks = 0; ks < BKC; ks += 16) {
            uint32_t ah[2][4], al[2][4];
            #pragma unroll
            for (int mt = 0; mt < 2; mt++) {
                ldsm_x4(ah[mt], aHi + mt * 1280 + ks * 2);
                ldsm_x4(al[mt], aLo + mt * 1280 + ks * 2);
            }
            #pragma unroll
            for (int np = 0; np < 4; np++) {
                uint32_t bh[4], bl[4];
                ldsm_x4(bh, bHi + np * 1280 + ks * 2);
                ldsm_x4(bl, bLo + np * 1280 + ks * 2);
                #pragma unroll
                for (int mt = 0; mt < 2; mt++) {
                    mma16816(acc[mt][2 * np],     ah[mt], bh[0], bh[1]);
                    mma16816(acc[mt][2 * np + 1], ah[mt], bh[2], bh[3]);
                    mma16816(acc[mt][2 * np],     al[mt], bh[0], bh[1]);
                    mma16816(acc[mt][2 * np + 1], al[mt], bh[2], bh[3]);
                    mma16816(acc[mt][2 * np],     ah[mt], bl[0], bl[1]);
                    mma16816(acc[mt][2 * np + 1], ah[mt], bl[2], bl[3]);
                }
            }
        }
        __syncthreads();
    }

    // epilogue
    const int lr = lane >> 2;
    const int lc = (lane & 3) * 2;
    #pragma unroll
    for (int mt = 0; mt < 2; mt++) {
        #pragma unroll
        for (int nt = 0; nt < 8; nt++) {
            #pragma unroll
            for (int hh = 0; hh < 2; hh++) {
                const int gr = m0 + wm * 32 + mt * 16 + lr + hh * 8;
                const int gc = n0 + wn * 64 + nt * 8 + lc;
                float v0 = acc[mt][nt][hh * 2 + 0] + bias[gc];
                float v1 = acc[mt][nt][hh * 2 + 1] + bias[gc + 1];
                const size_t go = (size_t)gr * N + gc;
                if (EPI == 1) {
                    v0 = 0.5f * v0 * (1.0f + erff(v0 * 0.70710678118654752f));
                    v1 = 0.5f * v1 * (1.0f + erff(v1 * 0.70710678118654752f));
                    __nv_bfloat16 h0 = __float2bfloat16(v0);
                    __nv_bfloat16 h1 = __float2bfloat16(v1);
                    __nv_bfloat16 l0 = __float2bfloat16(v0 - __bfloat162float(h0));
                    __nv_bfloat16 l1 = __float2bfloat16(v1 - __bfloat162float(h1));
                    uint32_t ph = (uint32_t)__bfloat16_as_ushort(h0) |
                                  ((uint32_t)__bfloat16_as_ushort(h1) << 16);
                    uint32_t pl = (uint32_t)__bfloat16_as_ushort(l0) |
                                  ((uint32_t)__bfloat16_as_ushort(l1) << 16);
                    ((uint32_t*)Chi)[go >> 1] = ph;
                    ((uint32_t*)Clo)[go >> 1] = pl;
                } else if (EPI == 2) {
                    float2 rr = *(const float2*)&res[go];
                    float2 o2 = make_float2(v0 * SURV_ + rr.x, v1 * SURV_ + rr.y);
                    *(float2*)&Cf[go] = o2;
                } else {  // EPI == 3: plain bias -> bf16
                    __nv_bfloat16 h0 = __float2bfloat16(v0);
                    __nv_bfloat16 h1 = __float2bfloat16(v1);
                    uint32_t pb = (uint32_t)__bfloat16_as_ushort(h0) |
                                  ((uint32_t)__bfloat16_as_ushort(h1) << 16);
                    ((uint32_t*)Chi)[go >> 1] = pb;
                }
            }
        }
    }
}

// ---------------- Flash attention (bf16 MMA, FA2 register softmax) ----------
// One CTA per (q_tile 64, head, batch); 128 threads (4 warps, 16 q-rows each).
#define FQT 64
#define LDQ 72

__global__ void __launch_bounds__(128) flash_mma(
    const __nv_bfloat16* __restrict__ qkv, const float* __restrict__ x,
    float* __restrict__ x1)
{
    __shared__ __align__(16) __nv_bfloat16 Qs[FQT][LDQ];
    __shared__ __align__(16) __nv_bfloat16 Ks[FQT][LDQ];
    __shared__ __align__(16) __nv_bfloat16 Vs[FQT][LDQ];

    const int t = threadIdx.x;
    const int lane = t & 31, wid = t >> 5;
    const int qt = blockIdx.x, h = blockIdx.y, b = blockIdx.z;
    const size_t base = (size_t)b * P_ * D3_;
    const int q0 = qt * FQT, hc = h * 64;

    // load Q tile (64x64 bf16)
    #pragma unroll
    for (int i = 0; i < 4; i++) {
        int idx = t + i * 128;
        int r = idx >> 3, c8 = (idx & 7) << 3;
        *(uint4*)&Qs[r][c8] =
            *(const uint4*)(qkv + base + (size_t)(q0 + r) * D3_ + hc + c8);
    }
    __syncthreads();

    // preload Q fragments (constant across kt)
    uint32_t qf[4][4];
    {
        const int qrow = wid * 16 + (lane & 15);
        const int qc = (lane >> 4) << 3;
        #pragma unroll
        for (int ks = 0; ks < 4; ks++)
            ldsm_x4(qf[ks], smem_u32(&Qs[qrow][ks * 16 + qc]));
    }

    float mrow[2] = {-1e30f, -1e30f};
    float lrow[2] = {0.f, 0.f};
    float o[8][4];
    #pragma unroll
    for (int i = 0; i < 8; i++)
        #pragma unroll
        for (int j = 0; j < 4; j++) o[i][j] = 0.f;

    const float SCL = 0.18033688011112042f;  // (1/8) * log2(e)

    const int krow = (lane & 7) + ((lane >> 4) << 3);
    const int kcol = ((lane >> 3) & 1) << 3;
    const int vrow = (lane & 7) + (((lane >> 3) & 1) << 3);
    const int vcol = (lane >> 4) << 3;

    for (int kt = 0; kt < P_ / FQT; kt++) {
        __syncthreads();
        const int k0 = kt * FQT;
        #pragma unroll
        for (int i = 0; i < 4; i++) {
            int idx = t + i * 128;
            int r = idx >> 3, c8 = (idx & 7) << 3;
            *(uint4*)&Ks[r][c8] =
                *(const uint4*)(qkv + base + (size_t)(k0 + r) * D3_ + D_ + hc + c8);
            *(uint4*)&Vs[r][c8] =
                *(const uint4*)(qkv + base + (size_t)(k0 + r) * D3_ + 2 * D_ + hc + c8);
        }
        __syncthreads();

        // S = Q @ K^T (raw, scale folded into exp)
        float s[8][4];
        #pragma unroll
        for (int i = 0; i < 8; i++)
            #pragma unroll
            for (int j = 0; j < 4; j++) s[i][j] = 0.f;
        #pragma unroll
        for (int ks = 0; ks < 4; ks++) {
            #pragma unroll
            for (int tp = 0; tp < 4; tp++) {
                uint32_t kf[4];
                ldsm_x4(kf, smem_u32(&Ks[tp * 16 + krow][ks * 16 + kcol]));
                mma16816(s[2 * tp],     qf[ks], kf[0], kf[1]);
                mma16816(s[2 * tp + 1], qf[ks], kf[2], kf[3]);
            }
        }

        // online softmax (rows lr and lr+8)
        float pm[2] = {-1e30f, -1e30f};
        #pragma unroll
        for (int nt = 0; nt < 8; nt++) {
            pm[0] = fmaxf(pm[0], fmaxf(s[nt][0], s[nt][1]));
            pm[1] = fmaxf(pm[1], fmaxf(s[nt][2], s[nt][3]));
        }
        #pragma unroll
        for (int w = 0; w < 2; w++) {
            pm[w] = fmaxf(pm[w], __shfl_xor_sync(0xffffffffu, pm[w], 1));
            pm[w] = fmaxf(pm[w], __shfl_xor_sync(0xffffffffu, pm[w], 2));
        }
        float mn[2], f[2], sum[2];
        #pragma unroll
        for (int w = 0; w < 2; w++) {
            mn[w] = fmaxf(mrow[w], pm[w]);
            f[w]  = ex2f((mrow[w] - mn[w]) * SCL);
            sum[w] = 0.f;
        }
        #pragma unroll
        for (int nt = 0; nt < 8; nt++) {
            s[nt][0] = ex2f((s[nt][0] - mn[0]) * SCL);
            s[nt][1] = ex2f((s[nt][1] - mn[0]) * SCL);
            s[nt][2] = ex2f((s[nt][2] - mn[1]) * SCL);
            s[nt][3] = ex2f((s[nt][3] - mn[1]) * SCL);
            sum[0] += s[nt][0] + s[nt][1];
            sum[1] += s[nt][2] + s[nt][3];
        }
        #pragma unroll
        for (int w = 0; w < 2; w++) {
            sum[w] += __shfl_xor_sync(0xffffffffu, sum[w], 1);
            sum[w] += __shfl_xor_sync(0xffffffffu, sum[w], 2);
            lrow[w] = lrow[w] * f[w] + sum[w];
            mrow[w] = mn[w];
        }
        #pragma unroll
        for (int nt = 0; nt < 8; nt++) {
            o[nt][0] *= f[0]; o[nt][1] *= f[0];
            o[nt][2] *= f[1]; o[nt][3] *= f[1];
        }

        // P fragments (bf16) from S accumulators — layout identity
        uint32_t pf[4][4];
        #pragma unroll
        for (int ks = 0; ks < 4; ks++) {
            pf[ks][0] = pack_bf16x2(s[2 * ks][0],     s[2 * ks][1]);
            pf[ks][1] = pack_bf16x2(s[2 * ks][2],     s[2 * ks][3]);
            pf[ks][2] = pack_bf16x2(s[2 * ks + 1][0], s[2 * ks + 1][1]);
            pf[ks][3] = pack_bf16x2(s[2 * ks + 1][2], s[2 * ks + 1][3]);
        }

        // O += P @ V  (V via ldmatrix.trans)
        #pragma unroll
        for (int ks = 0; ks < 4; ks++) {
            #pragma unroll
            for (int tp = 0; tp < 4; tp++) {
                uint32_t vf[4];
                ldsm_x4_t(vf, smem_u32(&Vs[ks * 16 + vrow][tp * 16 + vcol]));
                mma16816(o[2 * tp],     pf[ks], vf[0], vf[1]);
                mma16816(o[2 * tp + 1], pf[ks], vf[2], vf[3]);
            }
        }
    }

    // finalize: /l, *0.9, + residual x
    const float inv0 = 1.0f / lrow[0];
    const float inv1 = 1.0f / lrow[1];
    const int r0 = q0 + wid * 16 + (lane >> 2);
    const size_t row0 = ((size_t)b * P_ + r0) * D_ + hc + (lane & 3) * 2;
    const size_t row1 = row0 + 8 * D_;
    #pragma unroll
    for (int nt = 0; nt < 8; nt++) {
        float2 xa = *(const float2*)&x[row0 + nt * 8];
        float2 ra;
        ra.x = o[nt][0] * inv0 * SURV_ + xa.x;
        ra.y = o[nt][1] * inv0 * SURV_ + xa.y;
        *(float2*)&x1[row0 + nt * 8] = ra;
        float2 xb = *(const float2*)&x[row1 + nt * 8];
        float2 rb;
        rb.x = o[nt][2] * inv1 * SURV_ + xb.x;
        rb.y = o[nt][3] * inv1 * SURV_ + xb.y;
        *(float2*)&x1[row1 + nt * 8] = rb;
    }
}

// ---------------- launch ----------------------------------------------------
extern "C" void kernel_launch(void* const* d_in, const int* in_sizes, int n_in,
                              void* d_out, int out_size)
{
    const float* x     = (const float*)d_in[0];
    const float* ln1_g = (const float*)d_in[1];
    const float* ln1_b = (const float*)d_in[2];
    const float* w_qkv = (const float*)d_in[3];
    const float* b_qkv = (const float*)d_in[4];
    const float* ln2_g = (const float*)d_in[5];
    const float* ln2_b = (const float*)d_in[6];
    const float* w1    = (const float*)d_in[7];
    const float* b1    = (const float*)d_in[8];
    const float* w2    = (const float*)d_in[9];
    const float* b2    = (const float*)d_in[10];
    float* out = (float*)d_out;

    __nv_bfloat16 *h_hi, *h_lo, *qkvb, *ffn_hi, *ffn_lo;
    __nv_bfloat16 *wq_hi, *wq_lo, *w1_hi, *w1_lo, *w2_hi, *w2_lo;
    float *x1;
    cudaGetSymbolAddress((void**)&h_hi,   g_h_hi);
    cudaGetSymbolAddress((void**)&h_lo,   g_h_lo);
    cudaGetSymbolAddress((void**)&qkvb,   g_qkvb);
    cudaGetSymbolAddress((void**)&x1,     g_x1);
    cudaGetSymbolAddress((void**)&ffn_hi, g_ffn_hi);
    cudaGetSymbolAddress((void**)&ffn_lo, g_ffn_lo);
    cudaGetSymbolAddress((void**)&wq_hi,  g_wq_hi);
    cudaGetSymbolAddress((void**)&wq_lo,  g_wq_lo);
    cudaGetSymbolAddress((void**)&w1_hi,  g_w1_hi);
    cudaGetSymbolAddress((void**)&w1_lo,  g_w1_lo);
    cudaGetSymbolAddress((void**)&w2_hi,  g_w2_hi);
    cudaGetSymbolAddress((void**)&w2_lo,  g_w2_lo);

    cudaFuncSetAttribute(gemm_mma<1>,
                         cudaFuncAttributeMaxDynamicSharedMemorySize, GEMM_SMEM);
    cudaFuncSetAttribute(gemm_mma<2>,
                         cudaFuncAttributeMaxDynamicSharedMemorySize, GEMM_SMEM);
    cudaFuncSetAttribute(gemm_mma<3>,
                         cudaFuncAttributeMaxDynamicSharedMemorySize, GEMM_SMEM);

    // weight transpose + split
    wsplit_kernel<<<dim3(D3_ / 32, D_ / 32), 256>>>(w_qkv, wq_hi, wq_lo, D_, D3_);
    wsplit_kernel<<<dim3(DFF_ / 32, D_ / 32), 256>>>(w1, w1_hi, w1_lo, D_, DFF_);
    wsplit_kernel<<<dim3(D_ / 32, DFF_ / 32), 256>>>(w2, w2_hi, w2_lo, DFF_, D_);

    // 1) LN1 -> split bf16
    ln_split_kernel<<<NTOK, 256>>>(x, ln1_g, ln1_b, h_hi, h_lo);
    // 2) QKV projection -> bf16
    gemm_mma<3><<<dim3(D3_ / BN, NTOK / BM), 256, GEMM_SMEM>>>(
        h_hi, h_lo, wq_hi, wq_lo, b_qkv, nullptr,
        nullptr, qkvb, nullptr, NTOK, D3_, D_);
    // 3) attention + residual -> x1
    flash_mma<<<dim3(P_ / FQT, H_, B_), 128>>>(qkvb, x, x1);
    // 4) LN2 -> split bf16
    ln_split_kernel<<<NTOK, 256>>>(x1, ln2_g, ln2_b, h_hi, h_lo);
    // 5) MLP up + GELU -> split bf16
    gemm_mma<1><<<dim3(DFF_ / BN, NTOK / BM), 256, GEMM_SMEM>>>(
        h_hi, h_lo, w1_hi, w1_lo, b1, nullptr,
        nullptr, ffn_hi, ffn_lo, NTOK, DFF_, D_);
    // 6) MLP down + droppath + residual -> out
    gemm_mma<2><<<dim3(D_ / BN, NTOK / BM), 256, GEMM_SMEM>>>(
        ffn_hi, ffn_lo, w2_hi, w2_lo, b2, x1,
        out, nullptr, nullptr, NTOK, D_, DFF_);
}